// round 2
// baseline (speedup 1.0000x reference)
#include <cuda_runtime.h>
#include <math.h>

#define NN    50000
#define F_IN  256
#define D_HID 64
#define NH    8
#define HD    512      // NH * D_HID
#define NC    10
#define MAXE  850000

// ---------------- scratch (device globals: no allocs allowed) ----------------
__device__ float g_h1[NN * HD];          // layer-1 features [n][h][d]  (102.4 MB)
__device__ float g_xcat[NN * HD];        // layer-1 output / layer-2 input (102.4 MB)
__device__ float g_Wcat[F_IN * HD];      // packed W_heads as [k][h*64+d]
__device__ float g_s1[NN * NH];          // per-node per-head src score
__device__ float g_s2[NN * NH];          // per-node per-head dst score
__device__ int   g_cnt[NN];
__device__ int   g_rowstart[NN + 1];
__device__ int   g_cursor[NN];
__device__ int   g_edst[MAXE];
__device__ int   g_csrc[MAXE];
__device__ float g_eval1[MAXE * NH];     // per-(edge,head) attention weights (27.2 MB)
__device__ float g_eval2[MAXE];
__device__ float g_h2[NN * 16];          // layer-2 features, padded row of 16
__device__ float g_t1[NN];
__device__ float g_t2[NN];

__device__ __forceinline__ float eluf(float x) { return x > 0.f ? x : expm1f(x); }
__device__ __forceinline__ float att_e(float sc) {
    float lk = sc > 0.f ? sc : 0.2f * sc;   // leaky_relu(sc, 0.2)
    return expf(-lk);
}

// ---------------- small utility kernels ----------------
__global__ void k_zero_cnt() {
    int i = blockIdx.x * blockDim.x + threadIdx.x;
    if (i < NN) g_cnt[i] = 0;
}

__global__ void k_pack(const float* __restrict__ Wh) {
    int i = blockIdx.x * blockDim.x + threadIdx.x;   // over F_IN*HD
    if (i >= F_IN * HD) return;
    int k = i / HD;
    int col = i - k * HD;
    int h = col >> 6;
    int d = col & 63;
    g_Wcat[i] = Wh[h * (F_IN * D_HID) + k * D_HID + d];
}

__global__ void k_count(const int* __restrict__ src, int E) {
    int e = blockIdx.x * blockDim.x + threadIdx.x;
    if (e < E) atomicAdd(&g_cnt[src[e]], 1);
}

// single-block scan over NN counts -> rowstart (exclusive), cursor copy
__global__ void k_scan() {
    __shared__ int sh[1024];
    __shared__ int carry;
    int tid = threadIdx.x;
    if (tid == 0) { carry = 0; g_rowstart[0] = 0; }
    __syncthreads();
    for (int base = 0; base < NN; base += 1024) {
        int i = base + tid;
        int v = (i < NN) ? g_cnt[i] : 0;
        sh[tid] = v;
        __syncthreads();
        #pragma unroll
        for (int off = 1; off < 1024; off <<= 1) {
            int t = (tid >= off) ? sh[tid - off] : 0;
            __syncthreads();
            sh[tid] += t;
            __syncthreads();
        }
        int incl = carry + sh[tid];
        if (i < NN) {
            g_rowstart[i + 1] = incl;
            g_cursor[i] = incl - v;
        }
        __syncthreads();
        if (tid == 0) carry += sh[1023];
        __syncthreads();
    }
}

__global__ void k_scatter(const int* __restrict__ src, const int* __restrict__ dst, int E) {
    int e = blockIdx.x * blockDim.x + threadIdx.x;
    if (e < E) {
        int s = src[e];
        int p = atomicAdd(&g_cursor[s], 1);
        g_edst[p] = dst[e];
        g_csrc[p] = s;
    }
}

// ---------------- layer-1 GEMM: h1[50000,512] = x[50000,256] @ Wcat[256,512] --
__global__ void k_gemm1(const float* __restrict__ A) {
    __shared__ float As[16][132];   // [k][row], padded
    __shared__ float Bs[16][64];
    const int tid = threadIdx.x;
    const int tx = tid & 15;
    const int ty = tid >> 4;
    const int rowBase = blockIdx.y * 128;
    const int colBase = blockIdx.x * 64;
    const int a_row = tid >> 1;          // 0..127
    const int a_k   = (tid & 1) * 8;     // 0 or 8
    const int b_k   = tid >> 4;          // 0..15
    const int b_col = (tid & 15) * 4;
    const int gr = rowBase + a_row;

    float acc[8][4];
    #pragma unroll
    for (int i = 0; i < 8; i++)
        #pragma unroll
        for (int j = 0; j < 4; j++) acc[i][j] = 0.f;

    for (int k0 = 0; k0 < F_IN; k0 += 16) {
        float4 av0, av1;
        if (gr < NN) {
            const float* ap = A + (size_t)gr * F_IN + k0 + a_k;
            av0 = *(const float4*)(ap);
            av1 = *(const float4*)(ap + 4);
        } else {
            av0 = make_float4(0.f, 0.f, 0.f, 0.f);
            av1 = av0;
        }
        As[a_k + 0][a_row] = av0.x; As[a_k + 1][a_row] = av0.y;
        As[a_k + 2][a_row] = av0.z; As[a_k + 3][a_row] = av0.w;
        As[a_k + 4][a_row] = av1.x; As[a_k + 5][a_row] = av1.y;
        As[a_k + 6][a_row] = av1.z; As[a_k + 7][a_row] = av1.w;

        float4 bv = *(const float4*)(g_Wcat + (size_t)(k0 + b_k) * HD + colBase + b_col);
        *(float4*)&Bs[b_k][b_col] = bv;
        __syncthreads();

        #pragma unroll
        for (int k = 0; k < 16; k++) {
            float4 a0 = *(const float4*)&As[k][ty * 8];
            float4 a1 = *(const float4*)&As[k][ty * 8 + 4];
            float4 b  = *(const float4*)&Bs[k][tx * 4];
            float ar[8] = {a0.x, a0.y, a0.z, a0.w, a1.x, a1.y, a1.z, a1.w};
            float br[4] = {b.x, b.y, b.z, b.w};
            #pragma unroll
            for (int i = 0; i < 8; i++)
                #pragma unroll
                for (int j = 0; j < 4; j++) acc[i][j] += ar[i] * br[j];
        }
        __syncthreads();
    }

    #pragma unroll
    for (int i = 0; i < 8; i++) {
        int r = rowBase + ty * 8 + i;
        if (r < NN) {
            *(float4*)(g_h1 + (size_t)r * HD + colBase + tx * 4) =
                make_float4(acc[i][0], acc[i][1], acc[i][2], acc[i][3]);
        }
    }
}

// ---------------- per (node,head) score dots ----------------
__global__ void k_scores(const float* __restrict__ ah) {
    int warp = (blockIdx.x * blockDim.x + threadIdx.x) >> 5;
    int lane = threadIdx.x & 31;
    if (warp >= NN * NH) return;
    int n = warp >> 3;
    int h = warp & 7;
    const float* hp = g_h1 + (size_t)n * HD + h * 64;
    float2 hv = *(const float2*)(hp + lane * 2);
    float2 a1 = *(const float2*)(ah + h * 128 + lane * 2);
    float2 a2 = *(const float2*)(ah + h * 128 + 64 + lane * 2);
    float p1 = hv.x * a1.x + hv.y * a1.y;
    float p2 = hv.x * a2.x + hv.y * a2.y;
    #pragma unroll
    for (int off = 16; off; off >>= 1) {
        p1 += __shfl_xor_sync(0xffffffffu, p1, off);
        p2 += __shfl_xor_sync(0xffffffffu, p2, off);
    }
    if (lane == 0) { g_s1[warp] = p1; g_s2[warp] = p2; }
}

// ---------------- per-(edge,head) attention weights ----------------
__global__ void k_eval1(int E) {
    int idx = blockIdx.x * blockDim.x + threadIdx.x;
    if (idx >= E * NH) return;
    int p = idx >> 3;
    int h = idx & 7;
    int s = g_csrc[p];
    int d = g_edst[p];
    float sc = g_s1[s * NH + h] + g_s2[d * NH + h];
    g_eval1[idx] = att_e(sc);
}

// ---------------- layer-1 aggregation: one block (128 thr) per node ----------
__global__ void k_agg1() {
    int n = blockIdx.x;
    int t = threadIdx.x;            // 0..127
    int h = t >> 4;                 // head
    int q = t & 15;                 // quad within head (4 floats each)
    int start = g_rowstart[n];
    int end   = g_rowstart[n + 1];
    float4 acc = make_float4(0.f, 0.f, 0.f, 0.f);
    float rs = 0.f;
    for (int p = start; p < end; p++) {
        int d = g_edst[p];
        float e = g_eval1[(size_t)p * NH + h];
        float4 hv = *(const float4*)(g_h1 + (size_t)d * HD + h * 64 + q * 4);
        acc.x += e * hv.x; acc.y += e * hv.y;
        acc.z += e * hv.z; acc.w += e * hv.w;
        rs += e;
    }
    float inv = 1.f / rs;
    float4 o;
    o.x = eluf(acc.x * inv);
    o.y = eluf(acc.y * inv);
    o.z = eluf(acc.z * inv);
    o.w = eluf(acc.w * inv);
    *(float4*)(g_xcat + (size_t)n * HD + t * 4) = o;
}

// ---------------- layer-2 GEMM + score dots (warp per node) ------------------
__global__ void k_gemm2(const float* __restrict__ Wo, const float* __restrict__ ao) {
    __shared__ float Ws[HD * NC];
    __shared__ float as_[2 * NC];
    int tid = threadIdx.x;
    for (int i = tid; i < HD * NC; i += 256) Ws[i] = Wo[i];
    if (tid < 2 * NC) as_[tid] = ao[tid];
    __syncthreads();
    int warp = tid >> 5;
    int lane = tid & 31;
    int n = blockIdx.x * 8 + warp;
    if (n >= NN) return;
    float acc[NC];
    #pragma unroll
    for (int c = 0; c < NC; c++) acc[c] = 0.f;
    const float* xp = g_xcat + (size_t)n * HD;
    for (int k0 = 0; k0 < HD; k0 += 32) {
        float xv = xp[k0 + lane];
        const float* wrow = Ws + (k0 + lane) * NC;
        #pragma unroll
        for (int c = 0; c < NC; c++) acc[c] += xv * wrow[c];
    }
    #pragma unroll
    for (int c = 0; c < NC; c++)
        #pragma unroll
        for (int off = 16; off; off >>= 1)
            acc[c] += __shfl_xor_sync(0xffffffffu, acc[c], off);
    if (lane == 0) {
        float s1 = 0.f, s2 = 0.f;
        #pragma unroll
        for (int c = 0; c < NC; c++) {
            g_h2[n * 16 + c] = acc[c];
            s1 += acc[c] * as_[c];
            s2 += acc[c] * as_[NC + c];
        }
        g_t1[n] = s1;
        g_t2[n] = s2;
    }
}

__global__ void k_eval2(int E) {
    int p = blockIdx.x * blockDim.x + threadIdx.x;
    if (p >= E) return;
    float sc = g_t1[g_csrc[p]] + g_t2[g_edst[p]];
    g_eval2[p] = att_e(sc);
}

// ---------------- layer-2 aggregation + elu + log_softmax (warp per node) ----
__global__ void k_agg2(float* __restrict__ out) {
    int warp = (blockIdx.x * blockDim.x + threadIdx.x) >> 5;
    int lane = threadIdx.x & 31;
    if (warp >= NN) return;
    int n = warp;
    int start = g_rowstart[n];
    int end   = g_rowstart[n + 1];
    float acc = 0.f, rs = 0.f;
    for (int p = start; p < end; p++) {
        float ev = g_eval2[p];
        rs += ev;
        if (lane < NC) acc += ev * g_h2[g_edst[p] * 16 + lane];
    }
    float v = (lane < NC) ? eluf(acc / rs) : -1e30f;
    float m = v;
    #pragma unroll
    for (int off = 16; off; off >>= 1) m = fmaxf(m, __shfl_xor_sync(0xffffffffu, m, off));
    float ex = (lane < NC) ? expf(v - m) : 0.f;
    float sm = ex;
    #pragma unroll
    for (int off = 16; off; off >>= 1) sm += __shfl_xor_sync(0xffffffffu, sm, off);
    if (lane < NC) out[(size_t)n * NC + lane] = v - m - logf(sm);
}

// ---------------- launcher ----------------
extern "C" void kernel_launch(void* const* d_in, const int* in_sizes, int n_in,
                              void* d_out, int out_size) {
    const float* x    = (const float*)d_in[0];
    const int*   esrc = (const int*)d_in[1];
    const int*   edst = (const int*)d_in[2];
    const float* Wh   = (const float*)d_in[3];
    const float* ah   = (const float*)d_in[4];
    const float* Wo   = (const float*)d_in[5];
    const float* ao   = (const float*)d_in[6];
    float* out = (float*)d_out;
    const int E = in_sizes[1];

    k_zero_cnt<<<(NN + 255) / 256, 256>>>();
    k_pack<<<(F_IN * HD + 255) / 256, 256>>>(Wh);
    k_gemm1<<<dim3(HD / 64, (NN + 127) / 128), 256>>>(x);
    k_scores<<<(NN * NH + 7) / 8, 256>>>(ah);
    k_count<<<(E + 255) / 256, 256>>>(esrc, E);
    k_scan<<<1, 1024>>>();
    k_scatter<<<(E + 255) / 256, 256>>>(esrc, edst, E);
    k_eval1<<<(E * NH + 255) / 256, 256>>>(E);
    k_agg1<<<NN, 128>>>();
    k_gemm2<<<(NN + 7) / 8, 256>>>(Wo, ao);
    k_eval2<<<(E + 255) / 256, 256>>>(E);
    k_agg2<<<(NN + 7) / 8, 256>>>(out);
}

// round 6
// speedup vs baseline: 1.2097x; 1.2097x over previous
#include <cuda_runtime.h>
#include <cuda_bf16.h>
#include <math.h>

#define NN    50000
#define F_IN  256
#define D_HID 64
#define NH    8
#define HD    512      // NH * D_HID
#define NC    10
#define MAXE  850000

// ---------------- scratch (device globals: no allocs allowed) ----------------
__device__ float g_h1[NN * HD];          // layer-1 features [n][h][d]  (102.4 MB)
__device__ float g_xcat[NN * HD];        // layer-1 output / layer-2 input (102.4 MB)
__device__ __nv_bfloat16 g_Bhi[HD * F_IN];  // W packed [n=h*64+d][k], bf16 hi
__device__ __nv_bfloat16 g_Blo[HD * F_IN];  // bf16 lo residual
__device__ float g_s1[NN * NH];          // per-node per-head src score
__device__ float g_s2[NN * NH];          // per-node per-head dst score
__device__ int   g_cnt[NN];
__device__ int   g_rowstart[NN + 1];
__device__ int   g_cursor[NN];
__device__ int   g_incl[NN];
__device__ int   g_bsum[64];
__device__ int   g_boff[64];
__device__ int   g_edst[MAXE];
__device__ int   g_csrc[MAXE];
__device__ float g_eval1[MAXE * NH];     // per-(edge,head) attention weights (27.2 MB)
__device__ float g_eval2[MAXE];
__device__ float g_h2[NN * 16];          // layer-2 features, padded row of 16
__device__ float g_t1[NN];
__device__ float g_t2[NN];

__device__ __forceinline__ float eluf(float x) { return x > 0.f ? x : expm1f(x); }
__device__ __forceinline__ float att_e(float sc) {
    float lk = sc > 0.f ? sc : 0.2f * sc;   // leaky_relu(sc, 0.2)
    return expf(-lk);
}

// ---------------- small utility kernels ----------------
__global__ void k_zero_cnt() {
    int i = blockIdx.x * blockDim.x + threadIdx.x;
    if (i < NN) g_cnt[i] = 0;
}

// pack W_heads [H][F_IN][D_HID] -> bf16 hi/lo planes, layout [n][k] (n = h*64+d)
__global__ void k_pack(const float* __restrict__ Wh) {
    int i = blockIdx.x * blockDim.x + threadIdx.x;   // over HD*F_IN
    if (i >= HD * F_IN) return;
    int n = i >> 8;        // 0..511
    int k = i & 255;
    int h = n >> 6;
    int d = n & 63;
    float w = Wh[h * (F_IN * D_HID) + k * D_HID + d];
    __nv_bfloat16 hi = __float2bfloat16(w);
    float lo = w - __bfloat162float(hi);
    g_Bhi[i] = hi;
    g_Blo[i] = __float2bfloat16(lo);
}

__global__ void k_count(const int* __restrict__ src, int E) {
    int e = blockIdx.x * blockDim.x + threadIdx.x;
    if (e < E) atomicAdd(&g_cnt[src[e]], 1);
}

// hierarchical scan: per-block inclusive scan + block sums
__global__ void k_scan1() {
    __shared__ int sh[1024];
    int b = blockIdx.x, tid = threadIdx.x;
    int i = b * 1024 + tid;
    int v = (i < NN) ? g_cnt[i] : 0;
    sh[tid] = v;
    __syncthreads();
    #pragma unroll
    for (int off = 1; off < 1024; off <<= 1) {
        int t = (tid >= off) ? sh[tid - off] : 0;
        __syncthreads();
        sh[tid] += t;
        __syncthreads();
    }
    if (i < NN) g_incl[i] = sh[tid];
    if (tid == 1023) g_bsum[b] = sh[tid];
}

__global__ void k_scan2() {
    __shared__ int sh[64];
    int tid = threadIdx.x;
    const int nb = (NN + 1023) / 1024;
    int v = (tid < nb) ? g_bsum[tid] : 0;
    sh[tid] = v;
    __syncthreads();
    #pragma unroll
    for (int off = 1; off < 64; off <<= 1) {
        int t = (tid >= off) ? sh[tid - off] : 0;
        __syncthreads();
        sh[tid] += t;
        __syncthreads();
    }
    g_boff[tid] = sh[tid] - v;   // exclusive
}

__global__ void k_scan3() {
    int i = blockIdx.x * blockDim.x + threadIdx.x;
    if (i >= NN) return;
    int incl = g_incl[i] + g_boff[i >> 10];
    g_rowstart[i + 1] = incl;
    g_cursor[i] = incl - g_cnt[i];
    if (i == 0) g_rowstart[0] = 0;
}

__global__ void k_scatter(const int* __restrict__ src, const int* __restrict__ dst, int E) {
    int e = blockIdx.x * blockDim.x + threadIdx.x;
    if (e < E) {
        int s = src[e];
        int p = atomicAdd(&g_cursor[s], 1);
        g_edst[p] = dst[e];
        g_csrc[p] = s;
    }
}

// ---------------- layer-1 GEMM via tensor cores (split-bf16, 3 MMAs) ---------
// h1[50000,512] = x[50000,256] @ W[256,512], full ~fp32 accuracy via
// Ahi*Bhi + Ahi*Blo + Alo*Bhi.
#define BM 128
#define BN 128
#define BK 32
#define PADH 40   // smem row pitch in halves (80B: 16B-aligned, conflict-free frags)

__device__ __forceinline__ void mma16816(float* c, const unsigned* a, const unsigned* b) {
    asm volatile(
        "mma.sync.aligned.m16n8k16.row.col.f32.bf16.bf16.f32 "
        "{%0,%1,%2,%3}, {%4,%5,%6,%7}, {%8,%9}, {%0,%1,%2,%3};\n"
        : "+f"(c[0]), "+f"(c[1]), "+f"(c[2]), "+f"(c[3])
        : "r"(a[0]), "r"(a[1]), "r"(a[2]), "r"(a[3]), "r"(b[0]), "r"(b[1]));
}

__global__ void __launch_bounds__(256) k_gemm1_mma(const float* __restrict__ A) {
    __shared__ __nv_bfloat16 As_hi[BM * PADH];
    __shared__ __nv_bfloat16 As_lo[BM * PADH];
    __shared__ __nv_bfloat16 Bs_hi[BN * PADH];
    __shared__ __nv_bfloat16 Bs_lo[BN * PADH];

    const int tid = threadIdx.x;
    const int lane = tid & 31;
    const int warp = tid >> 5;
    const int wm = warp & 3;          // 4 m-warps, 32 rows each
    const int wn = warp >> 2;         // 2 n-warps, 64 cols each
    const int rowBase = blockIdx.y * BM;
    const int colBase = blockIdx.x * BN;

    const int gr = lane >> 2;         // 0..7
    const int t2 = (lane & 3) * 2;    // 0,2,4,6

    float acc[2][8][4];
    #pragma unroll
    for (int i = 0; i < 2; i++)
        #pragma unroll
        for (int j = 0; j < 8; j++)
            #pragma unroll
            for (int q = 0; q < 4; q++) acc[i][j][q] = 0.f;

    // A-load indices: thread loads 4x float4 from row (tid>>1), col seg (tid&1)*16
    const int a_row = tid >> 1;
    const int a_cs  = (tid & 1) * 16;
    const int a_g   = rowBase + a_row;
    const bool a_ok = (a_g < NN);

    for (int k0 = 0; k0 < F_IN; k0 += BK) {
        // ---- stage A tile (convert fp32 -> bf16 hi/lo) ----
        #pragma unroll
        for (int j = 0; j < 4; j++) {
            int c = a_cs + j * 4;
            float4 v = a_ok ? *(const float4*)(A + (size_t)a_g * F_IN + k0 + c)
                            : make_float4(0.f, 0.f, 0.f, 0.f);
            float vs[4] = {v.x, v.y, v.z, v.w};
            #pragma unroll
            for (int e = 0; e < 4; e++) {
                __nv_bfloat16 hi = __float2bfloat16(vs[e]);
                As_hi[a_row * PADH + c + e] = hi;
                As_lo[a_row * PADH + c + e] = __float2bfloat16(vs[e] - __bfloat162float(hi));
            }
        }
        // ---- stage B tile (bf16 planes, layout [n][k]) ----
        #pragma unroll
        for (int s = 0; s < 2; s++) {
            int chunk = tid + s * 256;        // 0..511 over 128 rows x 4 16B-chunks
            int u = chunk >> 2;
            int v = chunk & 3;
            const uint4* srch = (const uint4*)(g_Bhi + (size_t)(colBase + u) * F_IN + k0 + v * 8);
            const uint4* srcl = (const uint4*)(g_Blo + (size_t)(colBase + u) * F_IN + k0 + v * 8);
            *(uint4*)&Bs_hi[u * PADH + v * 8] = *srch;
            *(uint4*)&Bs_lo[u * PADH + v * 8] = *srcl;
        }
        __syncthreads();

        #pragma unroll
        for (int kk = 0; kk < BK; kk += 16) {
            unsigned ahi[2][4], alo[2][4];
            #pragma unroll
            for (int mi = 0; mi < 2; mi++) {
                int base = (wm * 32 + mi * 16 + gr) * PADH + kk + t2;
                ahi[mi][0] = *(const unsigned*)&As_hi[base];
                ahi[mi][1] = *(const unsigned*)&As_hi[base + 8 * PADH];
                ahi[mi][2] = *(const unsigned*)&As_hi[base + 8];
                ahi[mi][3] = *(const unsigned*)&As_hi[base + 8 * PADH + 8];
                alo[mi][0] = *(const unsigned*)&As_lo[base];
                alo[mi][1] = *(const unsigned*)&As_lo[base + 8 * PADH];
                alo[mi][2] = *(const unsigned*)&As_lo[base + 8];
                alo[mi][3] = *(const unsigned*)&As_lo[base + 8 * PADH + 8];
            }
            #pragma unroll
            for (int ni = 0; ni < 8; ni++) {
                int nb = (wn * 64 + ni * 8 + gr) * PADH + kk + t2;
                unsigned bhi[2], blo[2];
                bhi[0] = *(const unsigned*)&Bs_hi[nb];
                bhi[1] = *(const unsigned*)&Bs_hi[nb + 8];
                blo[0] = *(const unsigned*)&Bs_lo[nb];
                blo[1] = *(const unsigned*)&Bs_lo[nb + 8];
                #pragma unroll
                for (int mi = 0; mi < 2; mi++) {
                    mma16816(acc[mi][ni], ahi[mi], bhi);
                    mma16816(acc[mi][ni], ahi[mi], blo);
                    mma16816(acc[mi][ni], alo[mi], bhi);
                }
            }
        }
        __syncthreads();
    }

    // ---- epilogue ----
    #pragma unroll
    for (int mi = 0; mi < 2; mi++) {
        int r0 = rowBase + wm * 32 + mi * 16 + gr;
        int r1 = r0 + 8;
        #pragma unroll
        for (int ni = 0; ni < 8; ni++) {
            int col = colBase + wn * 64 + ni * 8 + t2;
            if (r0 < NN)
                *(float2*)(g_h1 + (size_t)r0 * HD + col) = make_float2(acc[mi][ni][0], acc[mi][ni][1]);
            if (r1 < NN)
                *(float2*)(g_h1 + (size_t)r1 * HD + col) = make_float2(acc[mi][ni][2], acc[mi][ni][3]);
        }
    }
}

// ---------------- per (node,head) score dots ----------------
__global__ void k_scores(const float* __restrict__ ah) {
    int warp = (blockIdx.x * blockDim.x + threadIdx.x) >> 5;
    int lane = threadIdx.x & 31;
    if (warp >= NN * NH) return;
    int n = warp >> 3;
    int h = warp & 7;
    const float* hp = g_h1 + (size_t)n * HD + h * 64;
    float2 hv = *(const float2*)(hp + lane * 2);
    float2 a1 = *(const float2*)(ah + h * 128 + lane * 2);
    float2 a2 = *(const float2*)(ah + h * 128 + 64 + lane * 2);
    float p1 = hv.x * a1.x + hv.y * a1.y;
    float p2 = hv.x * a2.x + hv.y * a2.y;
    #pragma unroll
    for (int off = 16; off; off >>= 1) {
        p1 += __shfl_xor_sync(0xffffffffu, p1, off);
        p2 += __shfl_xor_sync(0xffffffffu, p2, off);
    }
    if (lane == 0) { g_s1[warp] = p1; g_s2[warp] = p2; }
}

// ---------------- per-(edge,head) attention weights ----------------
__global__ void k_eval1(int E) {
    int idx = blockIdx.x * blockDim.x + threadIdx.x;
    if (idx >= E * NH) return;
    int p = idx >> 3;
    int h = idx & 7;
    int s = g_csrc[p];
    int d = g_edst[p];
    float sc = g_s1[s * NH + h] + g_s2[d * NH + h];
    g_eval1[idx] = att_e(sc);
}

// ---------------- layer-1 aggregation: one block (128 thr) per node ----------
__global__ void k_agg1() {
    int n = blockIdx.x;
    int t = threadIdx.x;            // 0..127
    int h = t >> 4;                 // head
    int q = t & 15;                 // quad within head (4 floats each)
    int start = g_rowstart[n];
    int end   = g_rowstart[n + 1];
    float4 acc = make_float4(0.f, 0.f, 0.f, 0.f);
    float rs = 0.f;
    for (int p = start; p < end; p++) {
        int d = g_edst[p];
        float e = g_eval1[(size_t)p * NH + h];
        float4 hv = *(const float4*)(g_h1 + (size_t)d * HD + h * 64 + q * 4);
        acc.x += e * hv.x; acc.y += e * hv.y;
        acc.z += e * hv.z; acc.w += e * hv.w;
        rs += e;
    }
    float inv = 1.f / rs;
    float4 o;
    o.x = eluf(acc.x * inv);
    o.y = eluf(acc.y * inv);
    o.z = eluf(acc.z * inv);
    o.w = eluf(acc.w * inv);
    *(float4*)(g_xcat + (size_t)n * HD + t * 4) = o;
}

// ---------------- layer-2 GEMM + score dots (warp per node) ------------------
__global__ void k_gemm2(const float* __restrict__ Wo, const float* __restrict__ ao) {
    __shared__ float Ws[HD * NC];
    __shared__ float as_[2 * NC];
    int tid = threadIdx.x;
    for (int i = tid; i < HD * NC; i += 256) Ws[i] = Wo[i];
    if (tid < 2 * NC) as_[tid] = ao[tid];
    __syncthreads();
    int warp = tid >> 5;
    int lane = tid & 31;
    int n = blockIdx.x * 8 + warp;
    if (n >= NN) return;
    float acc[NC];
    #pragma unroll
    for (int c = 0; c < NC; c++) acc[c] = 0.f;
    const float* xp = g_xcat + (size_t)n * HD;
    for (int k0 = 0; k0 < HD; k0 += 32) {
        float xv = xp[k0 + lane];
        const float* wrow = Ws + (k0 + lane) * NC;
        #pragma unroll
        for (int c = 0; c < NC; c++) acc[c] += xv * wrow[c];
    }
    #pragma unroll
    for (int c = 0; c < NC; c++)
        #pragma unroll
        for (int off = 16; off; off >>= 1)
            acc[c] += __shfl_xor_sync(0xffffffffu, acc[c], off);
    if (lane == 0) {
        float s1 = 0.f, s2 = 0.f;
        #pragma unroll
        for (int c = 0; c < NC; c++) {
            g_h2[n * 16 + c] = acc[c];
            s1 += acc[c] * as_[c];
            s2 += acc[c] * as_[NC + c];
        }
        g_t1[n] = s1;
        g_t2[n] = s2;
    }
}

__global__ void k_eval2(int E) {
    int p = blockIdx.x * blockDim.x + threadIdx.x;
    if (p >= E) return;
    float sc = g_t1[g_csrc[p]] + g_t2[g_edst[p]];
    g_eval2[p] = att_e(sc);
}

// ---------------- layer-2 aggregation + elu + log_softmax (warp per node) ----
__global__ void k_agg2(float* __restrict__ out) {
    int warp = (blockIdx.x * blockDim.x + threadIdx.x) >> 5;
    int lane = threadIdx.x & 31;
    if (warp >= NN) return;
    int n = warp;
    int start = g_rowstart[n];
    int end   = g_rowstart[n + 1];
    float acc = 0.f, rs = 0.f;
    for (int p = start; p < end; p++) {
        float ev = g_eval2[p];
        rs += ev;
        if (lane < NC) acc += ev * g_h2[g_edst[p] * 16 + lane];
    }
    float v = (lane < NC) ? eluf(acc / rs) : -1e30f;
    float m = v;
    #pragma unroll
    for (int off = 16; off; off >>= 1) m = fmaxf(m, __shfl_xor_sync(0xffffffffu, m, off));
    float ex = (lane < NC) ? expf(v - m) : 0.f;
    float sm = ex;
    #pragma unroll
    for (int off = 16; off; off >>= 1) sm += __shfl_xor_sync(0xffffffffu, sm, off);
    if (lane < NC) out[(size_t)n * NC + lane] = v - m - logf(sm);
}

// ---------------- launcher ----------------
extern "C" void kernel_launch(void* const* d_in, const int* in_sizes, int n_in,
                              void* d_out, int out_size) {
    const float* x    = (const float*)d_in[0];
    const int*   esrc = (const int*)d_in[1];
    const int*   edst = (const int*)d_in[2];
    const float* Wh   = (const float*)d_in[3];
    const float* ah   = (const float*)d_in[4];
    const float* Wo   = (const float*)d_in[5];
    const float* ao   = (const float*)d_in[6];
    float* out = (float*)d_out;
    const int E = in_sizes[1];

    k_zero_cnt<<<(NN + 255) / 256, 256>>>();
    k_pack<<<(HD * F_IN + 255) / 256, 256>>>(Wh);
    k_gemm1_mma<<<dim3(HD / BN, (NN + BM - 1) / BM), 256>>>(x);
    k_scores<<<(NN * NH + 7) / 8, 256>>>(ah);
    k_count<<<(E + 255) / 256, 256>>>(esrc, E);
    k_scan1<<<(NN + 1023) / 1024, 1024>>>();
    k_scan2<<<1, 64>>>();
    k_scan3<<<(NN + 255) / 256, 256>>>();
    k_scatter<<<(E + 255) / 256, 256>>>(esrc, edst, E);
    k_eval1<<<(E * NH + 255) / 256, 256>>>(E);
    k_agg1<<<NN, 128>>>();
    k_gemm2<<<(NN + 7) / 8, 256>>>(Wo, ao);
    k_eval2<<<(E + 255) / 256, 256>>>(E);
    k_agg2<<<(NN + 7) / 8, 256>>>(out);
}

// round 8
// speedup vs baseline: 1.2973x; 1.0724x over previous
#include <cuda_runtime.h>
#include <cuda_bf16.h>
#include <math.h>

#define NN    50000
#define F_IN  256
#define D_HID 64
#define NH    8
#define HD    512      // NH * D_HID
#define NC    10
#define MAXE  850000

// ---------------- scratch (device globals: no allocs allowed) ----------------
__device__ float g_h1[NN * HD];          // layer-1 features [n][h][d]  (102.4 MB)
__device__ float g_xcat[NN * HD];        // layer-1 output / layer-2 input (102.4 MB)
__device__ __nv_bfloat16 g_Bhi[HD * F_IN];  // W packed [n=h*64+d][k], bf16 hi
__device__ __nv_bfloat16 g_Blo[HD * F_IN];  // bf16 lo residual
__device__ float g_s1[NN * NH];          // per-node per-head src score
__device__ float g_s2[NN * NH];          // per-node per-head dst score
__device__ int   g_cnt[NN];
__device__ int   g_rowstart[NN + 1];
__device__ int   g_cursor[NN];
__device__ int   g_incl[NN];
__device__ int   g_bsum[64];
__device__ int   g_boff[64];
__device__ int   g_edst[MAXE];
__device__ float g_eval1[MAXE * NH];     // per-(edge,head) attention weights (27.2 MB)
__device__ float g_eval2[MAXE];
__device__ float g_h2[NN * 16];          // layer-2 features, padded row of 16
__device__ float g_t1[NN];
__device__ float g_t2[NN];

__device__ __forceinline__ float eluf(float x) { return x > 0.f ? x : expm1f(x); }
__device__ __forceinline__ float att_e(float sc) {
    float lk = sc > 0.f ? sc : 0.2f * sc;   // leaky_relu(sc, 0.2)
    return expf(-lk);
}

// ---------------- small utility kernels ----------------
__global__ void k_zero_cnt() {
    int i = blockIdx.x * blockDim.x + threadIdx.x;
    if (i < NN) g_cnt[i] = 0;
}

// pack W_heads [H][F_IN][D_HID] -> bf16 hi/lo planes, layout [n][k] (n = h*64+d)
__global__ void k_pack(const float* __restrict__ Wh) {
    int i = blockIdx.x * blockDim.x + threadIdx.x;   // over HD*F_IN
    if (i >= HD * F_IN) return;
    int n = i >> 8;        // 0..511
    int k = i & 255;
    int h = n >> 6;
    int d = n & 63;
    float w = Wh[h * (F_IN * D_HID) + k * D_HID + d];
    __nv_bfloat16 hi = __float2bfloat16(w);
    float lo = w - __bfloat162float(hi);
    g_Bhi[i] = hi;
    g_Blo[i] = __float2bfloat16(lo);
}

__global__ void k_count(const int* __restrict__ src, int E) {
    int e = blockIdx.x * blockDim.x + threadIdx.x;
    if (e < E) atomicAdd(&g_cnt[src[e]], 1);
}

// hierarchical scan: per-block inclusive scan + block sums
__global__ void k_scan1() {
    __shared__ int sh[1024];
    int b = blockIdx.x, tid = threadIdx.x;
    int i = b * 1024 + tid;
    int v = (i < NN) ? g_cnt[i] : 0;
    sh[tid] = v;
    __syncthreads();
    #pragma unroll
    for (int off = 1; off < 1024; off <<= 1) {
        int t = (tid >= off) ? sh[tid - off] : 0;
        __syncthreads();
        sh[tid] += t;
        __syncthreads();
    }
    if (i < NN) g_incl[i] = sh[tid];
    if (tid == 1023) g_bsum[b] = sh[tid];
}

__global__ void k_scan2() {
    __shared__ int sh[64];
    int tid = threadIdx.x;
    const int nb = (NN + 1023) / 1024;
    int v = (tid < nb) ? g_bsum[tid] : 0;
    sh[tid] = v;
    __syncthreads();
    #pragma unroll
    for (int off = 1; off < 64; off <<= 1) {
        int t = (tid >= off) ? sh[tid - off] : 0;
        __syncthreads();
        sh[tid] += t;
        __syncthreads();
    }
    g_boff[tid] = sh[tid] - v;   // exclusive
}

__global__ void k_scan3() {
    int i = blockIdx.x * blockDim.x + threadIdx.x;
    if (i >= NN) return;
    int incl = g_incl[i] + g_boff[i >> 10];
    g_rowstart[i + 1] = incl;
    g_cursor[i] = incl - g_cnt[i];
    if (i == 0) g_rowstart[0] = 0;
}

__global__ void k_scatter(const int* __restrict__ src, const int* __restrict__ dst, int E) {
    int e = blockIdx.x * blockDim.x + threadIdx.x;
    if (e < E) {
        int s = src[e];
        int p = atomicAdd(&g_cursor[s], 1);
        g_edst[p] = dst[e];
    }
}

// ---------------- layer-1 GEMM via tensor cores (split-bf16, 3 MMAs) ---------
// h1[50000,512] = x[50000,256] @ W[256,512], full ~fp32 accuracy via
// Ahi*Bhi + Ahi*Blo + Alo*Bhi. Epilogue also emits s1/s2 score dots.
#define BM 128
#define BN 128
#define BK 32
#define PADH 40   // smem row pitch in halves (80B: 16B-aligned, conflict-free frags)

__device__ __forceinline__ void mma16816(float* c, const unsigned* a, const unsigned* b) {
    asm volatile(
        "mma.sync.aligned.m16n8k16.row.col.f32.bf16.bf16.f32 "
        "{%0,%1,%2,%3}, {%4,%5,%6,%7}, {%8,%9}, {%0,%1,%2,%3};\n"
        : "+f"(c[0]), "+f"(c[1]), "+f"(c[2]), "+f"(c[3])
        : "r"(a[0]), "r"(a[1]), "r"(a[2]), "r"(a[3]), "r"(b[0]), "r"(b[1]));
}

__global__ void __launch_bounds__(256) k_gemm1_mma(const float* __restrict__ A,
                                                   const float* __restrict__ ah) {
    __shared__ __nv_bfloat16 As_hi[BM * PADH];
    __shared__ __nv_bfloat16 As_lo[BM * PADH];
    __shared__ __nv_bfloat16 Bs_hi[BN * PADH];
    __shared__ __nv_bfloat16 Bs_lo[BN * PADH];

    const int tid = threadIdx.x;
    const int lane = tid & 31;
    const int warp = tid >> 5;
    const int wm = warp & 3;          // 4 m-warps, 32 rows each
    const int wn = warp >> 2;         // 2 n-warps, 64 cols each
    const int rowBase = blockIdx.y * BM;
    const int colBase = blockIdx.x * BN;

    const int gr = lane >> 2;         // 0..7
    const int t2 = (lane & 3) * 2;    // 0,2,4,6

    float acc[2][8][4];
    #pragma unroll
    for (int i = 0; i < 2; i++)
        #pragma unroll
        for (int j = 0; j < 8; j++)
            #pragma unroll
            for (int q = 0; q < 4; q++) acc[i][j][q] = 0.f;

    // A-load indices: thread loads 4x float4 from row (tid>>1), col seg (tid&1)*16
    const int a_row = tid >> 1;
    const int a_cs  = (tid & 1) * 16;
    const int a_g   = rowBase + a_row;
    const bool a_ok = (a_g < NN);

    for (int k0 = 0; k0 < F_IN; k0 += BK) {
        // ---- stage A tile (convert fp32 -> bf16 hi/lo) ----
        #pragma unroll
        for (int j = 0; j < 4; j++) {
            int c = a_cs + j * 4;
            float4 v = a_ok ? *(const float4*)(A + (size_t)a_g * F_IN + k0 + c)
                            : make_float4(0.f, 0.f, 0.f, 0.f);
            float vs[4] = {v.x, v.y, v.z, v.w};
            #pragma unroll
            for (int e = 0; e < 4; e++) {
                __nv_bfloat16 hi = __float2bfloat16(vs[e]);
                As_hi[a_row * PADH + c + e] = hi;
                As_lo[a_row * PADH + c + e] = __float2bfloat16(vs[e] - __bfloat162float(hi));
            }
        }
        // ---- stage B tile (bf16 planes, layout [n][k]) ----
        #pragma unroll
        for (int s = 0; s < 2; s++) {
            int chunk = tid + s * 256;        // 0..511 over 128 rows x 4 16B-chunks
            int u = chunk >> 2;
            int v = chunk & 3;
            const uint4* srch = (const uint4*)(g_Bhi + (size_t)(colBase + u) * F_IN + k0 + v * 8);
            const uint4* srcl = (const uint4*)(g_Blo + (size_t)(colBase + u) * F_IN + k0 + v * 8);
            *(uint4*)&Bs_hi[u * PADH + v * 8] = *srch;
            *(uint4*)&Bs_lo[u * PADH + v * 8] = *srcl;
        }
        __syncthreads();

        #pragma unroll
        for (int kk = 0; kk < BK; kk += 16) {
            unsigned ahi[2][4], alo[2][4];
            #pragma unroll
            for (int mi = 0; mi < 2; mi++) {
                int base = (wm * 32 + mi * 16 + gr) * PADH + kk + t2;
                ahi[mi][0] = *(const unsigned*)&As_hi[base];
                ahi[mi][1] = *(const unsigned*)&As_hi[base + 8 * PADH];
                ahi[mi][2] = *(const unsigned*)&As_hi[base + 8];
                ahi[mi][3] = *(const unsigned*)&As_hi[base + 8 * PADH + 8];
                alo[mi][0] = *(const unsigned*)&As_lo[base];
                alo[mi][1] = *(const unsigned*)&As_lo[base + 8 * PADH];
                alo[mi][2] = *(const unsigned*)&As_lo[base + 8];
                alo[mi][3] = *(const unsigned*)&As_lo[base + 8 * PADH + 8];
            }
            #pragma unroll
            for (int ni = 0; ni < 8; ni++) {
                int nb = (wn * 64 + ni * 8 + gr) * PADH + kk + t2;
                unsigned bhi[2], blo[2];
                bhi[0] = *(const unsigned*)&Bs_hi[nb];
                bhi[1] = *(const unsigned*)&Bs_hi[nb + 8];
                blo[0] = *(const unsigned*)&Bs_lo[nb];
                blo[1] = *(const unsigned*)&Bs_lo[nb + 8];
                #pragma unroll
                for (int mi = 0; mi < 2; mi++) {
                    mma16816(acc[mi][ni], ahi[mi], bhi);
                    mma16816(acc[mi][ni], ahi[mi], blo);
                    mma16816(acc[mi][ni], alo[mi], bhi);
                }
            }
        }
        __syncthreads();
    }

    // ---- epilogue: store h1, and fused per-(row,head) score dots ----
    const int h = (colBase >> 6) + wn;     // this warp's head
    #pragma unroll
    for (int mi = 0; mi < 2; mi++) {
        int r0 = rowBase + wm * 32 + mi * 16 + gr;
        int r1 = r0 + 8;
        float p1a = 0.f, p2a = 0.f, p1b = 0.f, p2b = 0.f;
        #pragma unroll
        for (int ni = 0; ni < 8; ni++) {
            int col = colBase + wn * 64 + ni * 8 + t2;
            if (r0 < NN)
                *(float2*)(g_h1 + (size_t)r0 * HD + col) = make_float2(acc[mi][ni][0], acc[mi][ni][1]);
            if (r1 < NN)
                *(float2*)(g_h1 + (size_t)r1 * HD + col) = make_float2(acc[mi][ni][2], acc[mi][ni][3]);
            float2 a1v = *(const float2*)(ah + h * 128 + ni * 8 + t2);
            float2 a2v = *(const float2*)(ah + h * 128 + 64 + ni * 8 + t2);
            p1a += acc[mi][ni][0] * a1v.x + acc[mi][ni][1] * a1v.y;
            p2a += acc[mi][ni][0] * a2v.x + acc[mi][ni][1] * a2v.y;
            p1b += acc[mi][ni][2] * a1v.x + acc[mi][ni][3] * a1v.y;
            p2b += acc[mi][ni][2] * a2v.x + acc[mi][ni][3] * a2v.y;
        }
        // reduce across the 4-lane quad (lane&3)
        #pragma unroll
        for (int off = 1; off < 4; off <<= 1) {
            p1a += __shfl_xor_sync(0xffffffffu, p1a, off);
            p2a += __shfl_xor_sync(0xffffffffu, p2a, off);
            p1b += __shfl_xor_sync(0xffffffffu, p1b, off);
            p2b += __shfl_xor_sync(0xffffffffu, p2b, off);
        }
        if ((lane & 3) == 0) {
            if (r0 < NN) { g_s1[r0 * NH + h] = p1a; g_s2[r0 * NH + h] = p2a; }
            if (r1 < NN) { g_s1[r1 * NH + h] = p1b; g_s2[r1 * NH + h] = p2b; }
        }
    }
}

// ---------------- per-(edge,head) attention weights: warp per node ----------
__global__ void k_eval1(int dummy) {
    int warp = (blockIdx.x * blockDim.x + threadIdx.x) >> 5;
    int lane = threadIdx.x & 31;
    if (warp >= NN) return;
    int n = warp;
    int start = g_rowstart[n];
    int deg   = g_rowstart[n + 1] - start;
    int h = lane & 7;
    float s1v = g_s1[n * NH + h];
    int total = deg * NH;
    for (int j = lane; j < total; j += 32) {
        int p = start + (j >> 3);            // h == lane&7 (stride 32 preserves it)
        int d = g_edst[p];
        float sc = s1v + g_s2[d * NH + h];
        g_eval1[(size_t)p * NH + h] = att_e(sc);
    }
}

// ---------------- layer-1 aggregation: 256 thr per node, 2 edges in flight --
__global__ void __launch_bounds__(256) k_agg1() {
    __shared__ float s_red[128 * 5];
    int n = blockIdx.x;
    int t = threadIdx.x;            // 0..255
    int half = t >> 7;              // which edge of the interleaved pair
    int tt = t & 127;
    int h = tt >> 4;                // head
    int q = tt & 15;                // quad within head (4 floats each)
    int start = g_rowstart[n];
    int end   = g_rowstart[n + 1];
    float4 acc = make_float4(0.f, 0.f, 0.f, 0.f);
    float rs = 0.f;
    #pragma unroll 2
    for (int p = start + half; p < end; p += 2) {
        int d = g_edst[p];
        float e = g_eval1[(size_t)p * NH + h];
        float4 hv = *(const float4*)(g_h1 + (size_t)d * HD + h * 64 + q * 4);
        acc.x += e * hv.x; acc.y += e * hv.y;
        acc.z += e * hv.z; acc.w += e * hv.w;
        rs += e;
    }
    if (half == 1) {
        float* sp = s_red + tt * 5;
        sp[0] = acc.x; sp[1] = acc.y; sp[2] = acc.z; sp[3] = acc.w; sp[4] = rs;
    }
    __syncthreads();
    if (half == 0) {
        float* sp = s_red + tt * 5;
        acc.x += sp[0]; acc.y += sp[1]; acc.z += sp[2]; acc.w += sp[3]; rs += sp[4];
        float inv = 1.f / rs;
        float4 o;
        o.x = eluf(acc.x * inv);
        o.y = eluf(acc.y * inv);
        o.z = eluf(acc.z * inv);
        o.w = eluf(acc.w * inv);
        *(float4*)(g_xcat + (size_t)n * HD + tt * 4) = o;
    }
}

// ---------------- layer-2 GEMM + score dots (warp per node) ------------------
__global__ void k_gemm2(const float* __restrict__ Wo, const float* __restrict__ ao) {
    __shared__ float Ws[HD * NC];
    __shared__ float as_[2 * NC];
    int tid = threadIdx.x;
    for (int i = tid; i < HD * NC; i += 256) Ws[i] = Wo[i];
    if (tid < 2 * NC) as_[tid] = ao[tid];
    __syncthreads();
    int warp = tid >> 5;
    int lane = tid & 31;
    int n = blockIdx.x * 8 + warp;
    if (n >= NN) return;
    float acc[NC];
    #pragma unroll
    for (int c = 0; c < NC; c++) acc[c] = 0.f;
    const float* xp = g_xcat + (size_t)n * HD;
    for (int k0 = 0; k0 < HD; k0 += 32) {
        float xv = xp[k0 + lane];
        const float* wrow = Ws + (k0 + lane) * NC;
        #pragma unroll
        for (int c = 0; c < NC; c++) acc[c] += xv * wrow[c];
    }
    #pragma unroll
    for (int c = 0; c < NC; c++)
        #pragma unroll
        for (int off = 16; off; off >>= 1)
            acc[c] += __shfl_xor_sync(0xffffffffu, acc[c], off);
    if (lane == 0) {
        float s1 = 0.f, s2 = 0.f;
        #pragma unroll
        for (int c = 0; c < NC; c++) {
            g_h2[n * 16 + c] = acc[c];
            s1 += acc[c] * as_[c];
            s2 += acc[c] * as_[NC + c];
        }
        g_t1[n] = s1;
        g_t2[n] = s2;
    }
}

// warp per node: per-edge layer-2 attention weights (no src array needed)
__global__ void k_eval2(int dummy) {
    int warp = (blockIdx.x * blockDim.x + threadIdx.x) >> 5;
    int lane = threadIdx.x & 31;
    if (warp >= NN) return;
    int n = warp;
    int start = g_rowstart[n];
    int end   = g_rowstart[n + 1];
    float t1n = g_t1[n];
    for (int p = start + lane; p < end; p += 32) {
        g_eval2[p] = att_e(t1n + g_t2[g_edst[p]]);
    }
}

// ---------------- layer-2 aggregation + elu + log_softmax (warp per node) ----
__global__ void k_agg2(float* __restrict__ out) {
    int warp = (blockIdx.x * blockDim.x + threadIdx.x) >> 5;
    int lane = threadIdx.x & 31;
    if (warp >= NN) return;
    int n = warp;
    int start = g_rowstart[n];
    int end   = g_rowstart[n + 1];
    float acc = 0.f, rs = 0.f;
    for (int p = start; p < end; p++) {
        float ev = g_eval2[p];
        rs += ev;
        if (lane < NC) acc += ev * g_h2[g_edst[p] * 16 + lane];
    }
    float v = (lane < NC) ? eluf(acc / rs) : -1e30f;
    float m = v;
    #pragma unroll
    for (int off = 16; off; off >>= 1) m = fmaxf(m, __shfl_xor_sync(0xffffffffu, m, off));
    float ex = (lane < NC) ? expf(v - m) : 0.f;
    float sm = ex;
    #pragma unroll
    for (int off = 16; off; off >>= 1) sm += __shfl_xor_sync(0xffffffffu, sm, off);
    if (lane < NC) out[(size_t)n * NC + lane] = v - m - logf(sm);
}

// ---------------- launcher ----------------
extern "C" void kernel_launch(void* const* d_in, const int* in_sizes, int n_in,
                              void* d_out, int out_size) {
    const float* x    = (const float*)d_in[0];
    const int*   esrc = (const int*)d_in[1];
    const int*   edst = (const int*)d_in[2];
    const float* Wh   = (const float*)d_in[3];
    const float* ah   = (const float*)d_in[4];
    const float* Wo   = (const float*)d_in[5];
    const float* ao   = (const float*)d_in[6];
    float* out = (float*)d_out;
    const int E = in_sizes[1];

    k_zero_cnt<<<(NN + 255) / 256, 256>>>();
    k_pack<<<(HD * F_IN + 255) / 256, 256>>>(Wh);
    k_count<<<(E + 255) / 256, 256>>>(esrc, E);
    k_gemm1_mma<<<dim3(HD / BN, (NN + BM - 1) / BM), 256>>>(x, ah);
    k_scan1<<<(NN + 1023) / 1024, 1024>>>();
    k_scan2<<<1, 64>>>();
    k_scan3<<<(NN + 255) / 256, 256>>>();
    k_scatter<<<(E + 255) / 256, 256>>>(esrc, edst, E);
    k_eval1<<<(NN + 7) / 8, 256>>>(0);
    k_agg1<<<NN, 256>>>();
    k_gemm2<<<(NN + 7) / 8, 256>>>(Wo, ao);
    k_eval2<<<(NN + 7) / 8, 256>>>(0);
    k_agg2<<<(NN + 7) / 8, 256>>>(out);
}

// round 10
// speedup vs baseline: 1.6496x; 1.2715x over previous
#include <cuda_runtime.h>
#include <cuda_bf16.h>
#include <math.h>

#define NN    50000
#define NNP   50048    // padded to 128
#define F_IN  256
#define D_HID 64
#define NH    8
#define HD    512      // NH * D_HID
#define NC    10
#define MAXE  850000

// ---------------- scratch (device globals: no allocs allowed) ----------------
__device__ __nv_bfloat16 g_h1b[NNP * HD];   // layer-1 features bf16 (51.2 MB)
__device__ float g_xcat[NN * HD];           // layer-1 output / layer-2 input
__device__ __nv_bfloat16 g_Ahi[NNP * F_IN]; // x hi plane (25.6 MB)
__device__ __nv_bfloat16 g_Alo[NNP * F_IN]; // x lo plane
__device__ __nv_bfloat16 g_Bhi[HD * F_IN];  // W packed [n=h*64+d][k], bf16 hi
__device__ __nv_bfloat16 g_Blo[HD * F_IN];  // bf16 lo residual
__device__ float g_s1[NN * NH];
__device__ float g_s2[NN * NH];
__device__ int   g_cnt[NN];
__device__ int   g_rowstart[NN + 1];
__device__ int   g_cursor[NN];
__device__ int   g_incl[NN];
__device__ int   g_bsum[64];
__device__ int   g_boff[64];
__device__ int   g_edst[MAXE];
__device__ float g_eval1[MAXE * NH];        // per-(edge,head) attention weights
__device__ float g_eval2[MAXE];
__device__ float g_h2[NN * 16];
__device__ float g_t1[NN];
__device__ float g_t2[NN];

__device__ __forceinline__ float eluf(float x) { return x > 0.f ? x : expm1f(x); }
__device__ __forceinline__ float att_e(float sc) {
    float lk = sc > 0.f ? sc : 0.2f * sc;
    return expf(-lk);
}

// ---------------- small utility kernels ----------------
__global__ void k_zero_cnt() {
    int i = blockIdx.x * blockDim.x + threadIdx.x;
    if (i < NN) g_cnt[i] = 0;
}

// x[NN,256] fp32 -> bf16 hi/lo planes
__global__ void k_convA(const float* __restrict__ x) {
    int i = blockIdx.x * blockDim.x + threadIdx.x;   // over NN*F_IN/4
    if (i >= NN * F_IN / 4) return;
    float4 v = *(const float4*)(x + (size_t)i * 4);
    float vs[4] = {v.x, v.y, v.z, v.w};
    __nv_bfloat16 hi[4], lo[4];
    #pragma unroll
    for (int e = 0; e < 4; e++) {
        hi[e] = __float2bfloat16(vs[e]);
        lo[e] = __float2bfloat16(vs[e] - __bfloat162float(hi[e]));
    }
    *(uint2*)(g_Ahi + (size_t)i * 4) = *(uint2*)hi;
    *(uint2*)(g_Alo + (size_t)i * 4) = *(uint2*)lo;
}

// pack W_heads [H][F_IN][D_HID] -> bf16 hi/lo planes, layout [n][k]
__global__ void k_pack(const float* __restrict__ Wh) {
    int i = blockIdx.x * blockDim.x + threadIdx.x;
    if (i >= HD * F_IN) return;
    int n = i >> 8;
    int k = i & 255;
    int h = n >> 6;
    int d = n & 63;
    float w = Wh[h * (F_IN * D_HID) + k * D_HID + d];
    __nv_bfloat16 hi = __float2bfloat16(w);
    float lo = w - __bfloat162float(hi);
    g_Bhi[i] = hi;
    g_Blo[i] = __float2bfloat16(lo);
}

__global__ void k_count(const int* __restrict__ src, int E) {
    int e = blockIdx.x * blockDim.x + threadIdx.x;
    if (e < E) atomicAdd(&g_cnt[src[e]], 1);
}

__global__ void k_scan1() {
    __shared__ int sh[1024];
    int b = blockIdx.x, tid = threadIdx.x;
    int i = b * 1024 + tid;
    int v = (i < NN) ? g_cnt[i] : 0;
    sh[tid] = v;
    __syncthreads();
    #pragma unroll
    for (int off = 1; off < 1024; off <<= 1) {
        int t = (tid >= off) ? sh[tid - off] : 0;
        __syncthreads();
        sh[tid] += t;
        __syncthreads();
    }
    if (i < NN) g_incl[i] = sh[tid];
    if (tid == 1023) g_bsum[b] = sh[tid];
}

__global__ void k_scan2() {
    __shared__ int sh[64];
    int tid = threadIdx.x;
    const int nb = (NN + 1023) / 1024;
    int v = (tid < nb) ? g_bsum[tid] : 0;
    sh[tid] = v;
    __syncthreads();
    #pragma unroll
    for (int off = 1; off < 64; off <<= 1) {
        int t = (tid >= off) ? sh[tid - off] : 0;
        __syncthreads();
        sh[tid] += t;
        __syncthreads();
    }
    g_boff[tid] = sh[tid] - v;
}

__global__ void k_scan3() {
    int i = blockIdx.x * blockDim.x + threadIdx.x;
    if (i >= NN) return;
    int incl = g_incl[i] + g_boff[i >> 10];
    g_rowstart[i + 1] = incl;
    g_cursor[i] = incl - g_cnt[i];
    if (i == 0) g_rowstart[0] = 0;
}

__global__ void k_scatter(const int* __restrict__ src, const int* __restrict__ dst, int E) {
    int e = blockIdx.x * blockDim.x + threadIdx.x;
    if (e < E) {
        int s = src[e];
        int p = atomicAdd(&g_cursor[s], 1);
        g_edst[p] = dst[e];
    }
}

// ---------------- layer-1 GEMM: split-bf16 3xMMA, cp.async double-buffered ---
#define BM 128
#define BN 128
#define BK 32
#define PADH 40                 // smem row pitch in halves (80B, 16B-aligned)
#define PLANE (BM * PADH)       // halves per plane
#define STAGE_BYTES (4 * PLANE * 2)   // 40960
#define NTILES (F_IN / BK)      // 8

__device__ __forceinline__ void mma16816(float* c, const unsigned* a, const unsigned* b) {
    asm volatile(
        "mma.sync.aligned.m16n8k16.row.col.f32.bf16.bf16.f32 "
        "{%0,%1,%2,%3}, {%4,%5,%6,%7}, {%8,%9}, {%0,%1,%2,%3};\n"
        : "+f"(c[0]), "+f"(c[1]), "+f"(c[2]), "+f"(c[3])
        : "r"(a[0]), "r"(a[1]), "r"(a[2]), "r"(a[3]), "r"(b[0]), "r"(b[1]));
}

__device__ __forceinline__ void cpa16(unsigned dst, const void* src) {
    asm volatile("cp.async.cg.shared.global [%0], [%1], 16;\n" :: "r"(dst), "l"(src));
}
__device__ __forceinline__ void cpa_commit() {
    asm volatile("cp.async.commit_group;\n");
}
template <int N>
__device__ __forceinline__ void cpa_wait() {
    asm volatile("cp.async.wait_group %0;\n" :: "n"(N));
}

__global__ void __launch_bounds__(256) k_gemm1_mma(const float* __restrict__ ah) {
    extern __shared__ __nv_bfloat16 smem[];

    const int tid = threadIdx.x;
    const int lane = tid & 31;
    const int warp = tid >> 5;
    const int wm = warp & 3;          // 4 m-warps, 32 rows each
    const int wn = warp >> 2;         // 2 n-warps, 64 cols each
    const int rowBase = blockIdx.y * BM;
    const int colBase = blockIdx.x * BN;

    const int gr = lane >> 2;
    const int t2 = (lane & 3) * 2;

    float acc[2][8][4];
    #pragma unroll
    for (int i = 0; i < 2; i++)
        #pragma unroll
        for (int j = 0; j < 8; j++)
            #pragma unroll
            for (int q = 0; q < 4; q++) acc[i][j][q] = 0.f;

    // staging: 512 16B-chunks per plane; thread handles 2 chunks per plane
    const int c0 = tid, c1 = tid + 256;
    const int r0c = c0 >> 2, s0c = (c0 & 3) * 8;
    const int r1c = c1 >> 2, s1c = (c1 & 3) * 8;

    unsigned sbase = (unsigned)__cvta_generic_to_shared(smem);

    auto load_stage = [&](int it, int buf) {
        int k0 = it * BK;
        unsigned b = sbase + buf * STAGE_BYTES;
        // A hi/lo
        const __nv_bfloat16* a0h = g_Ahi + (size_t)(rowBase + r0c) * F_IN + k0 + s0c;
        const __nv_bfloat16* a1h = g_Ahi + (size_t)(rowBase + r1c) * F_IN + k0 + s1c;
        const __nv_bfloat16* a0l = g_Alo + (size_t)(rowBase + r0c) * F_IN + k0 + s0c;
        const __nv_bfloat16* a1l = g_Alo + (size_t)(rowBase + r1c) * F_IN + k0 + s1c;
        cpa16(b + (r0c * PADH + s0c) * 2, a0h);
        cpa16(b + (r1c * PADH + s1c) * 2, a1h);
        cpa16(b + (PLANE + r0c * PADH + s0c) * 2, a0l);
        cpa16(b + (PLANE + r1c * PADH + s1c) * 2, a1l);
        // B hi/lo
        const __nv_bfloat16* b0h = g_Bhi + (size_t)(colBase + r0c) * F_IN + k0 + s0c;
        const __nv_bfloat16* b1h = g_Bhi + (size_t)(colBase + r1c) * F_IN + k0 + s1c;
        const __nv_bfloat16* b0l = g_Blo + (size_t)(colBase + r0c) * F_IN + k0 + s0c;
        const __nv_bfloat16* b1l = g_Blo + (size_t)(colBase + r1c) * F_IN + k0 + s1c;
        cpa16(b + (2 * PLANE + r0c * PADH + s0c) * 2, b0h);
        cpa16(b + (2 * PLANE + r1c * PADH + s1c) * 2, b1h);
        cpa16(b + (3 * PLANE + r0c * PADH + s0c) * 2, b0l);
        cpa16(b + (3 * PLANE + r1c * PADH + s1c) * 2, b1l);
    };

    load_stage(0, 0);
    cpa_commit();

    for (int it = 0; it < NTILES; it++) {
        if (it + 1 < NTILES) {
            load_stage(it + 1, (it + 1) & 1);
            cpa_commit();
            cpa_wait<1>();
        } else {
            cpa_wait<0>();
        }
        __syncthreads();

        const __nv_bfloat16* As_hi = smem + (it & 1) * (STAGE_BYTES / 2);
        const __nv_bfloat16* As_lo = As_hi + PLANE;
        const __nv_bfloat16* Bs_hi = As_lo + PLANE;
        const __nv_bfloat16* Bs_lo = Bs_hi + PLANE;

        #pragma unroll
        for (int kk = 0; kk < BK; kk += 16) {
            unsigned ahi[2][4], alo[2][4];
            #pragma unroll
            for (int mi = 0; mi < 2; mi++) {
                int base = (wm * 32 + mi * 16 + gr) * PADH + kk + t2;
                ahi[mi][0] = *(const unsigned*)&As_hi[base];
                ahi[mi][1] = *(const unsigned*)&As_hi[base + 8 * PADH];
                ahi[mi][2] = *(const unsigned*)&As_hi[base + 8];
                ahi[mi][3] = *(const unsigned*)&As_hi[base + 8 * PADH + 8];
                alo[mi][0] = *(const unsigned*)&As_lo[base];
                alo[mi][1] = *(const unsigned*)&As_lo[base + 8 * PADH];
                alo[mi][2] = *(const unsigned*)&As_lo[base + 8];
                alo[mi][3] = *(const unsigned*)&As_lo[base + 8 * PADH + 8];
            }
            #pragma unroll
            for (int ni = 0; ni < 8; ni++) {
                int nb = (wn * 64 + ni * 8 + gr) * PADH + kk + t2;
                unsigned bhi[2], blo[2];
                bhi[0] = *(const unsigned*)&Bs_hi[nb];
                bhi[1] = *(const unsigned*)&Bs_hi[nb + 8];
                blo[0] = *(const unsigned*)&Bs_lo[nb];
                blo[1] = *(const unsigned*)&Bs_lo[nb + 8];
                #pragma unroll
                for (int mi = 0; mi < 2; mi++) {
                    mma16816(acc[mi][ni], ahi[mi], bhi);
                    mma16816(acc[mi][ni], ahi[mi], blo);
                    mma16816(acc[mi][ni], alo[mi], bhi);
                }
            }
        }
        __syncthreads();
    }

    // ---- epilogue: store bf16 h1, fused per-(row,head) score dots ----
    const int h = (colBase >> 6) + wn;
    #pragma unroll
    for (int mi = 0; mi < 2; mi++) {
        int r0 = rowBase + wm * 32 + mi * 16 + gr;
        int r1 = r0 + 8;
        float p1a = 0.f, p2a = 0.f, p1b = 0.f, p2b = 0.f;
        #pragma unroll
        for (int ni = 0; ni < 8; ni++) {
            int col = colBase + wn * 64 + ni * 8 + t2;
            if (r0 < NN)
                *(__nv_bfloat162*)(g_h1b + (size_t)r0 * HD + col) =
                    __float22bfloat162_rn(make_float2(acc[mi][ni][0], acc[mi][ni][1]));
            if (r1 < NN)
                *(__nv_bfloat162*)(g_h1b + (size_t)r1 * HD + col) =
                    __float22bfloat162_rn(make_float2(acc[mi][ni][2], acc[mi][ni][3]));
            float2 a1v = *(const float2*)(ah + h * 128 + ni * 8 + t2);
            float2 a2v = *(const float2*)(ah + h * 128 + 64 + ni * 8 + t2);
            p1a += acc[mi][ni][0] * a1v.x + acc[mi][ni][1] * a1v.y;
            p2a += acc[mi][ni][0] * a2v.x + acc[mi][ni][1] * a2v.y;
            p1b += acc[mi][ni][2] * a1v.x + acc[mi][ni][3] * a1v.y;
            p2b += acc[mi][ni][2] * a2v.x + acc[mi][ni][3] * a2v.y;
        }
        #pragma unroll
        for (int off = 1; off < 4; off <<= 1) {
            p1a += __shfl_xor_sync(0xffffffffu, p1a, off);
            p2a += __shfl_xor_sync(0xffffffffu, p2a, off);
            p1b += __shfl_xor_sync(0xffffffffu, p1b, off);
            p2b += __shfl_xor_sync(0xffffffffu, p2b, off);
        }
        if ((lane & 3) == 0) {
            if (r0 < NN) { g_s1[r0 * NH + h] = p1a; g_s2[r0 * NH + h] = p2a; }
            if (r1 < NN) { g_s1[r1 * NH + h] = p1b; g_s2[r1 * NH + h] = p2b; }
        }
    }
}

// ---------------- per-(edge,head) attention weights: warp per node ----------
__global__ void k_eval1(int dummy) {
    int warp = (blockIdx.x * blockDim.x + threadIdx.x) >> 5;
    int lane = threadIdx.x & 31;
    if (warp >= NN) return;
    int n = warp;
    int start = g_rowstart[n];
    int deg   = g_rowstart[n + 1] - start;
    int h = lane & 7;
    float s1v = g_s1[n * NH + h];
    int total = deg * NH;
    for (int j = lane; j < total; j += 32) {
        int p = start + (j >> 3);
        int d = g_edst[p];
        float sc = s1v + g_s2[d * NH + h];
        g_eval1[(size_t)p * NH + h] = att_e(sc);
    }
}

// ---------------- layer-1 aggregation: 256 thr per node, bf16 gather --------
__global__ void __launch_bounds__(256) k_agg1() {
    __shared__ float s_red[128 * 5];
    int n = blockIdx.x;
    int t = threadIdx.x;
    int half = t >> 7;
    int tt = t & 127;
    int h = tt >> 4;
    int q = tt & 15;
    int start = g_rowstart[n];
    int end   = g_rowstart[n + 1];
    float4 acc = make_float4(0.f, 0.f, 0.f, 0.f);
    float rs = 0.f;
    #pragma unroll 2
    for (int p = start + half; p < end; p += 2) {
        int d = g_edst[p];
        float e = g_eval1[(size_t)p * NH + h];
        uint2 raw = *(const uint2*)(g_h1b + (size_t)d * HD + h * 64 + q * 4);
        float2 f0 = __bfloat1622float2(*(__nv_bfloat162*)&raw.x);
        float2 f1 = __bfloat1622float2(*(__nv_bfloat162*)&raw.y);
        acc.x += e * f0.x; acc.y += e * f0.y;
        acc.z += e * f1.x; acc.w += e * f1.y;
        rs += e;
    }
    if (half == 1) {
        float* sp = s_red + tt * 5;
        sp[0] = acc.x; sp[1] = acc.y; sp[2] = acc.z; sp[3] = acc.w; sp[4] = rs;
    }
    __syncthreads();
    if (half == 0) {
        float* sp = s_red + tt * 5;
        acc.x += sp[0]; acc.y += sp[1]; acc.z += sp[2]; acc.w += sp[3]; rs += sp[4];
        float inv = 1.f / rs;
        float4 o;
        o.x = eluf(acc.x * inv);
        o.y = eluf(acc.y * inv);
        o.z = eluf(acc.z * inv);
        o.w = eluf(acc.w * inv);
        *(float4*)(g_xcat + (size_t)n * HD + tt * 4) = o;
    }
}

// ---------------- layer-2 GEMM + score dots (warp per node) ------------------
__global__ void k_gemm2(const float* __restrict__ Wo, const float* __restrict__ ao) {
    __shared__ float Ws[HD * NC];
    __shared__ float as_[2 * NC];
    int tid = threadIdx.x;
    for (int i = tid; i < HD * NC; i += 256) Ws[i] = Wo[i];
    if (tid < 2 * NC) as_[tid] = ao[tid];
    __syncthreads();
    int warp = tid >> 5;
    int lane = tid & 31;
    int n = blockIdx.x * 8 + warp;
    if (n >= NN) return;
    float acc[NC];
    #pragma unroll
    for (int c = 0; c < NC; c++) acc[c] = 0.f;
    const float* xp = g_xcat + (size_t)n * HD;
    for (int k0 = 0; k0 < HD; k0 += 32) {
        float xv = xp[k0 + lane];
        const float* wrow = Ws + (k0 + lane) * NC;
        #pragma unroll
        for (int c = 0; c < NC; c++) acc[c] += xv * wrow[c];
    }
    #pragma unroll
    for (int c = 0; c < NC; c++)
        #pragma unroll
        for (int off = 16; off; off >>= 1)
            acc[c] += __shfl_xor_sync(0xffffffffu, acc[c], off);
    if (lane == 0) {
        float s1 = 0.f, s2 = 0.f;
        #pragma unroll
        for (int c = 0; c < NC; c++) {
            g_h2[n * 16 + c] = acc[c];
            s1 += acc[c] * as_[c];
            s2 += acc[c] * as_[NC + c];
        }
        g_t1[n] = s1;
        g_t2[n] = s2;
    }
}

__global__ void k_eval2(int dummy) {
    int warp = (blockIdx.x * blockDim.x + threadIdx.x) >> 5;
    int lane = threadIdx.x & 31;
    if (warp >= NN) return;
    int n = warp;
    int start = g_rowstart[n];
    int end   = g_rowstart[n + 1];
    float t1n = g_t1[n];
    for (int p = start + lane; p < end; p += 32) {
        g_eval2[p] = att_e(t1n + g_t2[g_edst[p]]);
    }
}

// ---------------- layer-2 aggregation + elu + log_softmax (warp per node) ----
__global__ void k_agg2(float* __restrict__ out) {
    int warp = (blockIdx.x * blockDim.x + threadIdx.x) >> 5;
    int lane = threadIdx.x & 31;
    if (warp >= NN) return;
    int n = warp;
    int start = g_rowstart[n];
    int end   = g_rowstart[n + 1];
    float acc = 0.f, rs = 0.f;
    for (int p = start; p < end; p++) {
        float ev = g_eval2[p];
        rs += ev;
        if (lane < NC) acc += ev * g_h2[g_edst[p] * 16 + lane];
    }
    float v = (lane < NC) ? eluf(acc / rs) : -1e30f;
    float m = v;
    #pragma unroll
    for (int off = 16; off; off >>= 1) m = fmaxf(m, __shfl_xor_sync(0xffffffffu, m, off));
    float ex = (lane < NC) ? expf(v - m) : 0.f;
    float sm = ex;
    #pragma unroll
    for (int off = 16; off; off >>= 1) sm += __shfl_xor_sync(0xffffffffu, sm, off);
    if (lane < NC) out[(size_t)n * NC + lane] = v - m - logf(sm);
}

// ---------------- launcher ----------------
extern "C" void kernel_launch(void* const* d_in, const int* in_sizes, int n_in,
                              void* d_out, int out_size) {
    const float* x    = (const float*)d_in[0];
    const int*   esrc = (const int*)d_in[1];
    const int*   edst = (const int*)d_in[2];
    const float* Wh   = (const float*)d_in[3];
    const float* ah   = (const float*)d_in[4];
    const float* Wo   = (const float*)d_in[5];
    const float* ao   = (const float*)d_in[6];
    float* out = (float*)d_out;
    const int E = in_sizes[1];

    cudaFuncSetAttribute(k_gemm1_mma,
                         cudaFuncAttributeMaxDynamicSharedMemorySize,
                         2 * STAGE_BYTES);

    k_zero_cnt<<<(NN + 255) / 256, 256>>>();
    k_convA<<<(NN * F_IN / 4 + 255) / 256, 256>>>(x);
    k_pack<<<(HD * F_IN + 255) / 256, 256>>>(Wh);
    k_count<<<(E + 255) / 256, 256>>>(esrc, E);
    k_gemm1_mma<<<dim3(HD / BN, NNP / BM), 256, 2 * STAGE_BYTES>>>(ah);
    k_scan1<<<(NN + 1023) / 1024, 1024>>>();
    k_scan2<<<1, 64>>>();
    k_scan3<<<(NN + 255) / 256, 256>>>();
    k_scatter<<<(E + 255) / 256, 256>>>(esrc, edst, E);
    k_eval1<<<(NN + 7) / 8, 256>>>(0);
    k_agg1<<<NN, 256>>>();
    k_gemm2<<<(NN + 7) / 8, 256>>>(Wo, ao);
    k_eval2<<<(NN + 7) / 8, 256>>>(0);
    k_agg2<<<(NN + 7) / 8, 256>>>(out);
}